// round 15
// baseline (speedup 1.0000x reference)
#include <cuda_runtime.h>

// Problem constants
#define B_   8
#define C_   512
#define L_   2048
#define CQ_  64
#define KK_  1536

typedef unsigned short u16;
typedef unsigned int   u32;

// ---------------------------------------------------------------------------
// Scratch (device globals — allocation-free). 16B-aligned for cp.async.
// ---------------------------------------------------------------------------
static __device__ __align__(16) u16 xsh_hi[3][B_ * C_ * L_];
static __device__ __align__(16) u16 xsh_lo[3][B_ * C_ * L_];
static __device__ __align__(16) u16 wqk_hi[3 * 128 * 512];   // [t][m][c], q|k rows
static __device__ __align__(16) u16 wqk_lo[3 * 128 * 512];
static __device__ __align__(16) u16 wv_hi[3 * 512 * 512];    // [t][m][c]
static __device__ __align__(16) u16 wv_lo[3 * 512 * 512];
static __device__ __align__(16) u16 q_hi[B_ * CQ_ * L_], q_lo[B_ * CQ_ * L_];
static __device__ __align__(16) u16 k_hi[B_ * CQ_ * L_], k_lo[B_ * CQ_ * L_];
static __device__ __align__(16) u16 v_hi[B_ * C_ * L_],  v_lo[B_ * C_ * L_];
static __device__ float g_s[B_ * L_ * L_];                   // scores (fp32)
static __device__ __align__(16) u16 b_hi[B_ * L_ * L_], b_lo[B_ * L_ * L_];

// SMEM stage layout (per stage):
//   A_hi @ 0      A_lo @ 10240    (NT: 128 rows x 80B; T: 32 rows x 272B)
//   B_hi @ 20480  B_lo @ 29184    (T: 32 k-rows x 272B)
#define SA_STRIDE 80u
#define ST_STRIDE 272u
#define OFF_ALO  10240u
#define OFF_BHI  20480u
#define OFF_BLO  29184u
#define BLO_DELTA 8704u          // OFF_BLO - OFF_BHI
#define BUF_SZ   37888u
#define NSTAGE   3
#define SMEM_SZ  (NSTAGE * 37888)   // 113664 B/CTA -> 1 CTA x 512 thr/SM
#define NTHR     512

// ---------------------------------------------------------------------------
// PTX helpers
// ---------------------------------------------------------------------------
static __device__ __forceinline__ void ldsm4(unsigned r[4], unsigned addr) {
    asm volatile("ldmatrix.sync.aligned.m8n8.x4.shared.b16 {%0,%1,%2,%3}, [%4];"
                 : "=r"(r[0]), "=r"(r[1]), "=r"(r[2]), "=r"(r[3]) : "r"(addr));
}
static __device__ __forceinline__ void ldsm4t(unsigned r[4], unsigned addr) {
    asm volatile("ldmatrix.sync.aligned.m8n8.x4.trans.shared.b16 {%0,%1,%2,%3}, [%4];"
                 : "=r"(r[0]), "=r"(r[1]), "=r"(r[2]), "=r"(r[3]) : "r"(addr));
}
static __device__ __forceinline__ void mma16816(float d[4], const unsigned a[4],
                                                unsigned b0, unsigned b1) {
    asm volatile(
        "mma.sync.aligned.m16n8k16.row.col.f32.bf16.bf16.f32 "
        "{%0,%1,%2,%3}, {%4,%5,%6,%7}, {%8,%9}, {%0,%1,%2,%3};"
        : "+f"(d[0]), "+f"(d[1]), "+f"(d[2]), "+f"(d[3])
        : "r"(a[0]), "r"(a[1]), "r"(a[2]), "r"(a[3]), "r"(b0), "r"(b1));
}
static __device__ __forceinline__ void cpa16(unsigned s, const void* g) {
    asm volatile("cp.async.cg.shared.global [%0], [%1], 16;" :: "r"(s), "l"(g));
}
#define CP_COMMIT() asm volatile("cp.async.commit_group;" ::: "memory")
static __device__ __forceinline__ void cp_wait1() {
    asm volatile("cp.async.wait_group 1;" ::: "memory");
}

// fp32 pair -> hi (top-16 truncation) + lo (rn bf16 of exact residual)
static __device__ __forceinline__ void split_pack(float a0, float a1, u32& h, u32& l) {
    u32 b0 = __float_as_uint(a0), b1 = __float_as_uint(a1);
    asm("prmt.b32 %0, %1, %2, 0x7632;" : "=r"(h) : "r"(b0), "r"(b1));
    float h0 = __uint_as_float(b0 & 0xffff0000u);
    float h1 = __uint_as_float(b1 & 0xffff0000u);
    asm("cvt.rn.bf16x2.f32 %0, %1, %2;" : "=r"(l) : "f"(a1 - h1), "f"(a0 - h0));
}
static __device__ __forceinline__ void pack8(const float* v, uint4& H, uint4& L) {
    u32 h[4], l[4];
#pragma unroll
    for (int i = 0; i < 4; i++) split_pack(v[2 * i], v[2 * i + 1], h[i], l[i]);
    H = make_uint4(h[0], h[1], h[2], h[3]);
    L = make_uint4(l[0], l[1], l[2], l[3]);
}
static __device__ __forceinline__ void split_rn(float2 v, u32& h, u32& l) {
    asm("cvt.rn.bf16x2.f32 %0, %1, %2;" : "=r"(h) : "f"(v.y), "f"(v.x));
    float hx = __uint_as_float(h << 16);
    float hy = __uint_as_float(h & 0xffff0000u);
    asm("cvt.rn.bf16x2.f32 %0, %1, %2;" : "=r"(l) : "f"(v.y - hy), "f"(v.x - hx));
}

// ---------------------------------------------------------------------------
// Prep kernels
// ---------------------------------------------------------------------------
__global__ __launch_bounds__(256) void prep_x(const float* __restrict__ x)
{
    const int idx = blockIdx.x * 256 + threadIdx.x;      // over B*C*L/8
    const int base = idx * 8;
    const int row = base >> 11;                          // b*C + c
    const int l = base & (L_ - 1);
    const float* xr = x + (size_t)row * L_;

    float v[10];
    *(float4*)(v + 1) = *(const float4*)(xr + l);
    *(float4*)(v + 5) = *(const float4*)(xr + l + 4);
    v[0] = (l > 0) ? xr[l - 1] : 0.f;
    v[9] = (l + 8 < L_) ? xr[l + 8] : 0.f;

    const size_t o = (size_t)row * L_ + l;
#pragma unroll
    for (int t = 0; t < 3; t++) {        // xsh[t][j] = x[j + t - 1]
        uint4 H, L;
        pack8(v + t, H, L);
        *(uint4*)(&xsh_hi[t][o]) = H;
        *(uint4*)(&xsh_lo[t][o]) = L;
    }
}

__global__ __launch_bounds__(256) void prep_wqk(const float* __restrict__ Wq,
                                                const float* __restrict__ Wk)
{
    const int idx = blockIdx.x * 256 + threadIdx.x;      // 3*128*64
    const int c8 = idx & 63, m = (idx >> 6) & 127, t = idx >> 13;
    const float* src = ((m < CQ_) ? (Wq + m * KK_) : (Wk + (m - CQ_) * KK_)) + c8 * 24 + t;
    float v[8];
#pragma unroll
    for (int i = 0; i < 8; i++) v[i] = src[i * 3];
    uint4 H, L;
    pack8(v, H, L);
    const int o = (t * 128 + m) * 512 + c8 * 8;
    *(uint4*)(&wqk_hi[o]) = H;
    *(uint4*)(&wqk_lo[o]) = L;
}

__global__ __launch_bounds__(256) void prep_wv(const float* __restrict__ Wv)
{
    const int idx = blockIdx.x * 256 + threadIdx.x;      // 3*512*64
    const int c8 = idx & 63, m = (idx >> 6) & 511, t = idx >> 15;
    const float* src = Wv + m * KK_ + c8 * 24 + t;
    float v[8];
#pragma unroll
    for (int i = 0; i < 8; i++) v[i] = src[i * 3];
    uint4 H, L;
    pack8(v, H, L);
    const int o = (t * 512 + m) * 512 + c8 * 8;
    *(uint4*)(&wv_hi[o]) = H;
    *(uint4*)(&wv_lo[o]) = L;
}

// ---------------------------------------------------------------------------
// cp.async tile issue helpers (512 threads: one 16B cp per tile per thread)
// ---------------------------------------------------------------------------
static __device__ __forceinline__ void cpA_NT(unsigned buf, int tid,
                                              const u16* hi, const u16* lo,
                                              size_t rstride) {
    const int m = tid >> 2, s = tid & 3;                 // 128 rows x 4 segs
    const unsigned sm = buf + (unsigned)m * SA_STRIDE + (unsigned)s * 16u;
    const size_t go = (size_t)m * rstride + s * 8;
    cpa16(sm,           hi + go);
    cpa16(sm + OFF_ALO, lo + go);
}
// ldelta = smem distance from hi tile to lo tile (A: OFF_ALO, B: BLO_DELTA).
static __device__ __forceinline__ void cpT(unsigned buf, int tid,
                                           const u16* hi, const u16* lo,
                                           size_t rstride, unsigned ldelta) {
    const int kc = tid >> 4, s = tid & 15;               // 32 k-rows x 16 segs
    const unsigned sm = buf + (unsigned)kc * ST_STRIDE + (unsigned)s * 16u;
    const size_t go = (size_t)kc * rstride + s * 8;
    cpa16(sm,          hi + go);
    cpa16(sm + ldelta, lo + go);
}

// ---------------------------------------------------------------------------
// Per-problem structs
// ---------------------------------------------------------------------------
struct PConv {                   // merged conv: y=0..3 -> v rows, y=4 -> q|k rows
    static constexpr int NCH = 48;
    static constexpr bool A_T = false;
    __device__ void issue(unsigned buf, int ch, int tid) const {
        const int b = blockIdx.z, l0 = blockIdx.x * 128, y = blockIdx.y;
        const int t = ch >> 4, c0 = (ch & 15) * 32;
        const u16* Ah;
        const u16* Al;
        if (y == 4) {
            Ah = wqk_hi + (t * 128) * 512 + c0;
            Al = wqk_lo + (t * 128) * 512 + c0;
        } else {
            Ah = wv_hi + (t * 512 + y * 128) * 512 + c0;
            Al = wv_lo + (t * 512 + y * 128) * 512 + c0;
        }
        cpA_NT(buf, tid, Ah, Al, 512);
        const size_t bo = ((size_t)(b * C_ + c0)) * L_ + l0;
        cpT(buf + OFF_BHI, tid, xsh_hi[t] + bo, xsh_lo[t] + bo, L_, BLO_DELTA);
    }
    __device__ float scale() const { return 1.f; }
    __device__ void store2(int m, int col, float2 v) const {
        const int b = blockIdx.z, l0 = blockIdx.x * 128, y = blockIdx.y;
        u32 h, l;
        split_rn(v, h, l);
        if (y == 4) {
            const size_t off = ((size_t)(b * CQ_ + (m & 63))) * L_ + l0 + col;
            if (m < CQ_) { *(u32*)(q_hi + off) = h; *(u32*)(q_lo + off) = l; }
            else         { *(u32*)(k_hi + off) = h; *(u32*)(k_lo + off) = l; }
        } else {
            const size_t off = ((size_t)(b * C_ + y * 128 + m)) * L_ + l0 + col;
            *(u32*)(v_hi + off) = h;
            *(u32*)(v_lo + off) = l;
        }
    }
};

struct PScores {                 // D[i,j] = sum_c q[c,i]*k[c,j], K=64
    static constexpr int NCH = 2;
    static constexpr bool A_T = true;
    __device__ void issue(unsigned buf, int ch, int tid) const {
        const int b = blockIdx.z, j0 = blockIdx.x * 128, i0 = blockIdx.y * 128;
        const size_t ao = ((size_t)(b * CQ_ + ch * 32)) * L_ + i0;
        cpT(buf,           tid, q_hi + ao, q_lo + ao, L_, OFF_ALO);
        const size_t bo = ((size_t)(b * CQ_ + ch * 32)) * L_ + j0;
        cpT(buf + OFF_BHI, tid, k_hi + bo, k_lo + bo, L_, BLO_DELTA);
    }
    __device__ float scale() const { return 1.f; }
    __device__ void store2(int m, int col, float2 v) const {
        const int b = blockIdx.z, j0 = blockIdx.x * 128, i0 = blockIdx.y * 128;
        float* row = g_s + (size_t)b * L_ * L_ + (size_t)(i0 + m) * L_ + j0;
        *(float2*)(row + col) = v;
    }
};

struct POut {                    // out[c,j] = gamma * sum_l v[c,l]*beta[l,j], K=2048
    const float* gamma;
    float* out;
    static constexpr int NCH = 64;
    static constexpr bool A_T = false;
    __device__ void issue(unsigned buf, int ch, int tid) const {
        const int b = blockIdx.z, j0 = blockIdx.x * 128, c0 = blockIdx.y * 128;
        const size_t ao = ((size_t)(b * C_ + c0)) * L_ + ch * 32;
        cpA_NT(buf, tid, v_hi + ao, v_lo + ao, L_);
        const size_t bo = ((size_t)b * L_ + ch * 32) * L_ + j0;
        cpT(buf + OFF_BHI, tid, b_hi + bo, b_lo + bo, L_, BLO_DELTA);
    }
    __device__ float scale() const { return __ldg(gamma); }
    __device__ void store2(int m, int col, float2 v) const {
        const int b = blockIdx.z, j0 = blockIdx.x * 128, c0 = blockIdx.y * 128;
        float* row = out + ((size_t)(b * C_ + c0 + m)) * L_ + j0;
        *(float2*)(row + col) = v;
    }
};

// ---------------------------------------------------------------------------
// 16-warp (512-thread) mma core: 128x128 CTA tile, 32x32 warp tile,
// 3-stage cp.async pipeline, one barrier per chunk, 3-term hi/lo split.
// 4 warps per SMSP -> latency hiding without instruction-order gymnastics.
// ---------------------------------------------------------------------------
template <class P>
__global__ __launch_bounds__(NTHR, 1) void mma_kernel(P prm)
{
    extern __shared__ __align__(16) char smem[];
    const unsigned sb = (unsigned)__cvta_generic_to_shared(smem);

    const int tid  = threadIdx.x;
    const int lane = tid & 31;
    const int wid  = tid >> 5;          // 0..15
    const int wm   = wid >> 2;          // 0..3 (m, 32 rows each)
    const int wn   = wid & 3;           // 0..3 (n, 32 cols each)

    float acc[2][4][4];
#pragma unroll
    for (int a = 0; a < 2; a++)
#pragma unroll
        for (int b = 0; b < 4; b++)
#pragma unroll
            for (int c = 0; c < 4; c++) acc[a][b][c] = 0.f;

    const unsigned mNT    = (unsigned)((lane & 7) + ((lane >> 3) & 1) * 8);
    const unsigned ksel   = (unsigned)((lane >> 4) & 1);
    const unsigned krowT  = (unsigned)(ksel * 8 + (lane & 7));
    const unsigned chalfT = (unsigned)(((lane >> 3) & 1) * 8);

    // Prologue: stage chunks 0 and 1 (one commit-group each).
    prm.issue(sb, 0, tid);
    CP_COMMIT();
    if (P::NCH > 1) prm.issue(sb + BUF_SZ, 1, tid);
    CP_COMMIT();

    int stage = 0;                       // ch % NSTAGE
    int wstage = 2;                      // (ch+2) % NSTAGE
    for (int ch = 0; ch < P::NCH; ch++) {
        cp_wait1();                      // chunk ch landed
        __syncthreads();                 // all warps done reading buf[wstage]

        // Prefetch chunk ch+2 now (buf freed by the barrier above).
        if (ch + 2 < P::NCH)
            prm.issue(sb + (unsigned)wstage * BUF_SZ, ch + 2, tid);
        CP_COMMIT();                     // empty group when nothing issued

        const unsigned base = sb + (unsigned)stage * BUF_SZ;

#pragma unroll
        for (int ks = 0; ks < 2; ks++) {
            unsigned bh[2][4], bl[2][4];
            const unsigned kbB = ((unsigned)(ks * 16) + krowT) * ST_STRIDE;
#pragma unroll
            for (int n2 = 0; n2 < 2; n2++) {
                const unsigned col = ((unsigned)(wn * 32 + n2 * 16) + chalfT) * 2u;
                ldsm4t(bh[n2], base + OFF_BHI + kbB + col);
                ldsm4t(bl[n2], base + OFF_BLO + kbB + col);
            }
#pragma unroll
            for (int mi = 0; mi < 2; mi++) {
                unsigned ah4[4], al4[4];
                if (P::A_T) {
                    const unsigned kb  = ((unsigned)(ks * 16) + krowT) * ST_STRIDE;
                    const unsigned col = ((unsigned)(wm * 32 + mi * 16) + chalfT) * 2u;
                    ldsm4t(ah4, base + kb + col);
                    ldsm4t(al4, base + OFF_ALO + kb + col);
                } else {
                    const unsigned row = (unsigned)(wm * 32 + mi * 16) + mNT;
                    const unsigned o   = row * SA_STRIDE + (unsigned)(ks * 32) + ksel * 16u;
                    ldsm4(ah4, base + o);
                    ldsm4(al4, base + OFF_ALO + o);
                }
                // hh, hl, lh: same-acc distance 4 (R12's measured-best order)
                mma16816(acc[mi][0], ah4, bh[0][0], bh[0][2]);
                mma16816(acc[mi][1], ah4, bh[0][1], bh[0][3]);
                mma16816(acc[mi][2], ah4, bh[1][0], bh[1][2]);
                mma16816(acc[mi][3], ah4, bh[1][1], bh[1][3]);

                mma16816(acc[mi][0], ah4, bl[0][0], bl[0][2]);
                mma16816(acc[mi][1], ah4, bl[0][1], bl[0][3]);
                mma16816(acc[mi][2], ah4, bl[1][0], bl[1][2]);
                mma16816(acc[mi][3], ah4, bl[1][1], bl[1][3]);

                mma16816(acc[mi][0], al4, bh[0][0], bh[0][2]);
                mma16816(acc[mi][1], al4, bh[0][1], bh[0][3]);
                mma16816(acc[mi][2], al4, bh[1][0], bh[1][2]);
                mma16816(acc[mi][3], al4, bh[1][1], bh[1][3]);
            }
        }

        stage  = (stage  == NSTAGE - 1) ? 0 : stage + 1;
        wstage = (wstage == NSTAGE - 1) ? 0 : wstage + 1;
    }

    const float s = prm.scale();
#pragma unroll
    for (int mi = 0; mi < 2; mi++) {
#pragma unroll
        for (int rr = 0; rr < 2; rr++) {
            const int r = wm * 32 + mi * 16 + (lane >> 2) + rr * 8;
#pragma unroll
            for (int ni = 0; ni < 4; ni++) {
                const int col = wn * 32 + ni * 8 + (lane & 3) * 2;
                float2 v;
                v.x = acc[mi][ni][2 * rr]     * s;
                v.y = acc[mi][ni][2 * rr + 1] * s;
                prm.store2(r, col, v);
            }
        }
    }
}

// ---------------------------------------------------------------------------
// Softmax over axis i of g_s[b, i, j]; writes beta as bf16 hi/lo.
// ---------------------------------------------------------------------------
__global__ __launch_bounds__(256) void softmax_kernel()
{
    __shared__ float redm[256];
    __shared__ float reds[256];

    const int b  = blockIdx.y;
    const int j0 = blockIdx.x * 32;
    const int tid = threadIdx.x;
    const int jj = tid & 31;
    const int ig = tid >> 5;

    const size_t cb = (size_t)b * L_ * L_ + j0 + jj;
    const float* sbp = g_s + cb;

    float m0 = -1e30f, s0 = 0.f, m1 = -1e30f, s1 = 0.f;
    for (int i = ig; i < L_; i += 16) {
        const float v0 = sbp[(size_t)i * L_];
        const float v1 = sbp[(size_t)(i + 8) * L_];
        float nm = fmaxf(m0, v0);
        s0 = s0 * __expf(m0 - nm) + __expf(v0 - nm);
        m0 = nm;
        nm = fmaxf(m1, v1);
        s1 = s1 * __expf(m1 - nm) + __expf(v1 - nm);
        m1 = nm;
    }
    {
        const float nm = fmaxf(m0, m1);
        s0 = s0 * __expf(m0 - nm) + s1 * __expf(m1 - nm);
        m0 = nm;
    }
    redm[tid] = m0;
    reds[tid] = s0;
    __syncthreads();

    float M = -1e30f, S = 0.f;
#pragma unroll
    for (int g = 0; g < 8; g++) {
        const float mm = redm[g * 32 + jj];
        const float ss = reds[g * 32 + jj];
        const float nm = fmaxf(M, mm);
        S = S * __expf(M - nm) + ss * __expf(mm - nm);
        M = nm;
    }
    const float inv = 1.f / S;

    for (int i = ig; i < L_; i += 16) {
#pragma unroll
        for (int u = 0; u < 2; u++) {
            const size_t idx = cb + (size_t)(i + u * 8) * L_;
            const float val = __expf(g_s[idx] - M) * inv;
            u16 hs;
            asm("cvt.rn.bf16.f32 %0, %1;" : "=h"(hs) : "f"(val));
            const float hf = __uint_as_float((u32)hs << 16);
            u16 ls;
            asm("cvt.rn.bf16.f32 %0, %1;" : "=h"(ls) : "f"(val - hf));
            b_hi[idx] = hs;
            b_lo[idx] = ls;
        }
    }
}

// ---------------------------------------------------------------------------
extern "C" void kernel_launch(void* const* d_in, const int* in_sizes, int n_in,
                              void* d_out, int out_size)
{
    const float* x     = (const float*)d_in[0];
    const float* Wq    = (const float*)d_in[1];
    const float* Wk    = (const float*)d_in[2];
    const float* Wv    = (const float*)d_in[3];
    const float* gamma = (const float*)d_in[4];
    float* out = (float*)d_out;

    cudaFuncSetAttribute(mma_kernel<PConv>,
                         cudaFuncAttributeMaxDynamicSharedMemorySize, SMEM_SZ);
    cudaFuncSetAttribute(mma_kernel<PScores>,
                         cudaFuncAttributeMaxDynamicSharedMemorySize, SMEM_SZ);
    cudaFuncSetAttribute(mma_kernel<POut>,
                         cudaFuncAttributeMaxDynamicSharedMemorySize, SMEM_SZ);

    prep_x  <<<B_ * C_ * L_ / 8 / 256, 256>>>(x);
    prep_wqk<<<3 * 128 * 64 / 256,     256>>>(Wq, Wk);
    prep_wv <<<3 * 512 * 64 / 256,     256>>>(Wv);

    mma_kernel<PConv>  <<<dim3(L_ / 128, 5, B_),        NTHR, SMEM_SZ>>>(PConv{});
    mma_kernel<PScores><<<dim3(L_ / 128, L_ / 128, B_), NTHR, SMEM_SZ>>>(PScores{});
    softmax_kernel     <<<dim3(L_ / 32, B_),            256>>>();
    mma_kernel<POut>   <<<dim3(L_ / 128, C_ / 128, B_), NTHR, SMEM_SZ>>>(POut{gamma, out});
}

// round 16
// speedup vs baseline: 1.0198x; 1.0198x over previous
#include <cuda_runtime.h>
#include <cuda_fp16.h>

// Problem constants
#define B_   8
#define C_   512
#define L_   2048
#define CQ_  64
#define KK_  1536

typedef unsigned short u16;
typedef unsigned int   u32;

#define LO_SCALE   2048.0f        // 2^11: keeps fp16 lo residuals in normal range
#define LO_INV     (1.0f / 2048.0f)

// ---------------------------------------------------------------------------
// Scratch (device globals — allocation-free). 16B-aligned for cp.async.
// All hi/lo arrays hold fp16; lo tiles are pre-scaled by LO_SCALE.
// ---------------------------------------------------------------------------
static __device__ __align__(16) u16 xsh_hi[3][B_ * C_ * L_];
static __device__ __align__(16) u16 xsh_lo[3][B_ * C_ * L_];
static __device__ __align__(16) u16 wqk_hi[3 * 128 * 512];   // [t][m][c], q|k rows
static __device__ __align__(16) u16 wqk_lo[3 * 128 * 512];
static __device__ __align__(16) u16 wv_hi[3 * 512 * 512];    // [t][m][c]
static __device__ __align__(16) u16 wv_lo[3 * 512 * 512];
static __device__ __align__(16) u16 q_hi[B_ * CQ_ * L_], q_lo[B_ * CQ_ * L_];
static __device__ __align__(16) u16 k_hi[B_ * CQ_ * L_], k_lo[B_ * CQ_ * L_];
static __device__ __align__(16) u16 v_hi[B_ * C_ * L_],  v_lo[B_ * C_ * L_];
static __device__ float g_s[B_ * L_ * L_];                   // scores (fp32)
static __device__ __align__(16) u16 b_hi[B_ * L_ * L_], b_lo[B_ * L_ * L_];

// SMEM stage layout (per stage):
//   A_hi @ 0      A_lo @ 10240    (NT: 128 rows x 80B; T: 32 rows x 272B)
//   B_hi @ 20480  B_lo @ 29184    (T: 32 k-rows x 272B)
#define SA_STRIDE 80u
#define ST_STRIDE 272u
#define OFF_ALO  10240u
#define OFF_BHI  20480u
#define OFF_BLO  29184u
#define BLO_DELTA 8704u          // OFF_BLO - OFF_BHI
#define BUF_SZ   37888u
#define NSTAGE   3
#define SMEM_SZ  (NSTAGE * 37888)   // 113664 B/CTA -> 1 CTA x 512 thr/SM
#define NTHR     512

// ---------------------------------------------------------------------------
// PTX helpers
// ---------------------------------------------------------------------------
static __device__ __forceinline__ void ldsm4(unsigned r[4], unsigned addr) {
    asm volatile("ldmatrix.sync.aligned.m8n8.x4.shared.b16 {%0,%1,%2,%3}, [%4];"
                 : "=r"(r[0]), "=r"(r[1]), "=r"(r[2]), "=r"(r[3]) : "r"(addr));
}
static __device__ __forceinline__ void ldsm4t(unsigned r[4], unsigned addr) {
    asm volatile("ldmatrix.sync.aligned.m8n8.x4.trans.shared.b16 {%0,%1,%2,%3}, [%4];"
                 : "=r"(r[0]), "=r"(r[1]), "=r"(r[2]), "=r"(r[3]) : "r"(addr));
}
// fp16 operands, fp32 accumulator (full-precision main term)
static __device__ __forceinline__ void mma_f32acc(float d[4], const unsigned a[4],
                                                  unsigned b0, unsigned b1) {
    asm volatile(
        "mma.sync.aligned.m16n8k16.row.col.f32.f16.f16.f32 "
        "{%0,%1,%2,%3}, {%4,%5,%6,%7}, {%8,%9}, {%0,%1,%2,%3};"
        : "+f"(d[0]), "+f"(d[1]), "+f"(d[2]), "+f"(d[3])
        : "r"(a[0]), "r"(a[1]), "r"(a[2]), "r"(a[3]), "r"(b0), "r"(b1));
}
// fp16 operands, fp16 accumulator (correction terms; hypothesized 2x rate)
static __device__ __forceinline__ void mma_f16acc(u32 d[2], const unsigned a[4],
                                                  unsigned b0, unsigned b1) {
    asm volatile(
        "mma.sync.aligned.m16n8k16.row.col.f16.f16.f16.f16 "
        "{%0,%1}, {%2,%3,%4,%5}, {%6,%7}, {%0,%1};"
        : "+r"(d[0]), "+r"(d[1])
        : "r"(a[0]), "r"(a[1]), "r"(a[2]), "r"(a[3]), "r"(b0), "r"(b1));
}
static __device__ __forceinline__ void cpa16(unsigned s, const void* g) {
    asm volatile("cp.async.cg.shared.global [%0], [%1], 16;" :: "r"(s), "l"(g));
}
#define CP_COMMIT() asm volatile("cp.async.commit_group;" ::: "memory")
static __device__ __forceinline__ void cp_wait1() {
    asm volatile("cp.async.wait_group 1;" ::: "memory");
}

// fp32 pair -> hi (rn fp16) + lo (rn fp16 of residual, scaled by LO_SCALE)
static __device__ __forceinline__ void split_pack(float a0, float a1, u32& h, u32& l) {
    asm("cvt.rn.f16x2.f32 %0, %1, %2;" : "=r"(h) : "f"(a1), "f"(a0));
    float h0, h1;
    asm("{ .reg .f16 lo, hi;\n\t mov.b32 {lo, hi}, %2;\n\t"
        "cvt.f32.f16 %0, lo;\n\t cvt.f32.f16 %1, hi; }"
        : "=f"(h0), "=f"(h1) : "r"(h));
    asm("cvt.rn.f16x2.f32 %0, %1, %2;"
        : "=r"(l) : "f"((a1 - h1) * LO_SCALE), "f"((a0 - h0) * LO_SCALE));
}
static __device__ __forceinline__ void pack8(const float* v, uint4& H, uint4& L) {
    u32 h[4], l[4];
#pragma unroll
    for (int i = 0; i < 4; i++) split_pack(v[2 * i], v[2 * i + 1], h[i], l[i]);
    H = make_uint4(h[0], h[1], h[2], h[3]);
    L = make_uint4(l[0], l[1], l[2], l[3]);
}
// corr half2 reg -> two floats
static __device__ __forceinline__ void h2f2(u32 c, float& c0, float& c1) {
    asm("{ .reg .f16 lo, hi;\n\t mov.b32 {lo, hi}, %2;\n\t"
        "cvt.f32.f16 %0, lo;\n\t cvt.f32.f16 %1, hi; }"
        : "=f"(c0), "=f"(c1) : "r"(c));
}

// ---------------------------------------------------------------------------
// Prep kernels
// ---------------------------------------------------------------------------
__global__ __launch_bounds__(256) void prep_x(const float* __restrict__ x)
{
    const int idx = blockIdx.x * 256 + threadIdx.x;      // over B*C*L/8
    const int base = idx * 8;
    const int row = base >> 11;                          // b*C + c
    const int l = base & (L_ - 1);
    const float* xr = x + (size_t)row * L_;

    float v[10];
    *(float4*)(v + 1) = *(const float4*)(xr + l);
    *(float4*)(v + 5) = *(const float4*)(xr + l + 4);
    v[0] = (l > 0) ? xr[l - 1] : 0.f;
    v[9] = (l + 8 < L_) ? xr[l + 8] : 0.f;

    const size_t o = (size_t)row * L_ + l;
#pragma unroll
    for (int t = 0; t < 3; t++) {        // xsh[t][j] = x[j + t - 1]
        uint4 H, L;
        pack8(v + t, H, L);
        *(uint4*)(&xsh_hi[t][o]) = H;
        *(uint4*)(&xsh_lo[t][o]) = L;
    }
}

__global__ __launch_bounds__(256) void prep_wqk(const float* __restrict__ Wq,
                                                const float* __restrict__ Wk)
{
    const int idx = blockIdx.x * 256 + threadIdx.x;      // 3*128*64
    const int c8 = idx & 63, m = (idx >> 6) & 127, t = idx >> 13;
    const float* src = ((m < CQ_) ? (Wq + m * KK_) : (Wk + (m - CQ_) * KK_)) + c8 * 24 + t;
    float v[8];
#pragma unroll
    for (int i = 0; i < 8; i++) v[i] = src[i * 3];
    uint4 H, L;
    pack8(v, H, L);
    const int o = (t * 128 + m) * 512 + c8 * 8;
    *(uint4*)(&wqk_hi[o]) = H;
    *(uint4*)(&wqk_lo[o]) = L;
}

__global__ __launch_bounds__(256) void prep_wv(const float* __restrict__ Wv)
{
    const int idx = blockIdx.x * 256 + threadIdx.x;      // 3*512*64
    const int c8 = idx & 63, m = (idx >> 6) & 511, t = idx >> 15;
    const float* src = Wv + m * KK_ + c8 * 24 + t;
    float v[8];
#pragma unroll
    for (int i = 0; i < 8; i++) v[i] = src[i * 3];
    uint4 H, L;
    pack8(v, H, L);
    const int o = (t * 512 + m) * 512 + c8 * 8;
    *(uint4*)(&wv_hi[o]) = H;
    *(uint4*)(&wv_lo[o]) = L;
}

// ---------------------------------------------------------------------------
// cp.async tile issue helpers (512 threads: one 16B cp per tile per thread)
// ---------------------------------------------------------------------------
static __device__ __forceinline__ void cpA_NT(unsigned buf, int tid,
                                              const u16* hi, const u16* lo,
                                              size_t rstride) {
    const int m = tid >> 2, s = tid & 3;                 // 128 rows x 4 segs
    const unsigned sm = buf + (unsigned)m * SA_STRIDE + (unsigned)s * 16u;
    const size_t go = (size_t)m * rstride + s * 8;
    cpa16(sm,           hi + go);
    cpa16(sm + OFF_ALO, lo + go);
}
// ldelta = smem distance from hi tile to lo tile (A: OFF_ALO, B: BLO_DELTA).
static __device__ __forceinline__ void cpT(unsigned buf, int tid,
                                           const u16* hi, const u16* lo,
                                           size_t rstride, unsigned ldelta) {
    const int kc = tid >> 4, s = tid & 15;               // 32 k-rows x 16 segs
    const unsigned sm = buf + (unsigned)kc * ST_STRIDE + (unsigned)s * 16u;
    const size_t go = (size_t)kc * rstride + s * 8;
    cpa16(sm,          hi + go);
    cpa16(sm + ldelta, lo + go);
}

// ---------------------------------------------------------------------------
// Per-problem structs
// ---------------------------------------------------------------------------
struct PConv {                   // merged conv: y=0..3 -> v rows, y=4 -> q|k rows
    static constexpr int NCH = 48;
    static constexpr bool A_T = false;
    __device__ void issue(unsigned buf, int ch, int tid) const {
        const int b = blockIdx.z, l0 = blockIdx.x * 128, y = blockIdx.y;
        const int t = ch >> 4, c0 = (ch & 15) * 32;
        const u16* Ah;
        const u16* Al;
        if (y == 4) {
            Ah = wqk_hi + (t * 128) * 512 + c0;
            Al = wqk_lo + (t * 128) * 512 + c0;
        } else {
            Ah = wv_hi + (t * 512 + y * 128) * 512 + c0;
            Al = wv_lo + (t * 512 + y * 128) * 512 + c0;
        }
        cpA_NT(buf, tid, Ah, Al, 512);
        const size_t bo = ((size_t)(b * C_ + c0)) * L_ + l0;
        cpT(buf + OFF_BHI, tid, xsh_hi[t] + bo, xsh_lo[t] + bo, L_, BLO_DELTA);
    }
    __device__ float scale() const { return 1.f; }
    __device__ void store2(int m, int col, float2 v) const {
        const int b = blockIdx.z, l0 = blockIdx.x * 128, y = blockIdx.y;
        u32 h, l;
        split_pack(v.x, v.y, h, l);
        if (y == 4) {
            const size_t off = ((size_t)(b * CQ_ + (m & 63))) * L_ + l0 + col;
            if (m < CQ_) { *(u32*)(q_hi + off) = h; *(u32*)(q_lo + off) = l; }
            else         { *(u32*)(k_hi + off) = h; *(u32*)(k_lo + off) = l; }
        } else {
            const size_t off = ((size_t)(b * C_ + y * 128 + m)) * L_ + l0 + col;
            *(u32*)(v_hi + off) = h;
            *(u32*)(v_lo + off) = l;
        }
    }
};

struct PScores {                 // D[i,j] = sum_c q[c,i]*k[c,j], K=64
    static constexpr int NCH = 2;
    static constexpr bool A_T = true;
    __device__ void issue(unsigned buf, int ch, int tid) const {
        const int b = blockIdx.z, j0 = blockIdx.x * 128, i0 = blockIdx.y * 128;
        const size_t ao = ((size_t)(b * CQ_ + ch * 32)) * L_ + i0;
        cpT(buf,           tid, q_hi + ao, q_lo + ao, L_, OFF_ALO);
        const size_t bo = ((size_t)(b * CQ_ + ch * 32)) * L_ + j0;
        cpT(buf + OFF_BHI, tid, k_hi + bo, k_lo + bo, L_, BLO_DELTA);
    }
    __device__ float scale() const { return 1.f; }
    __device__ void store2(int m, int col, float2 v) const {
        const int b = blockIdx.z, j0 = blockIdx.x * 128, i0 = blockIdx.y * 128;
        float* row = g_s + (size_t)b * L_ * L_ + (size_t)(i0 + m) * L_ + j0;
        *(float2*)(row + col) = v;
    }
};

struct POut {                    // out[c,j] = gamma * sum_l v[c,l]*beta[l,j], K=2048
    const float* gamma;
    float* out;
    static constexpr int NCH = 64;
    static constexpr bool A_T = false;
    __device__ void issue(unsigned buf, int ch, int tid) const {
        const int b = blockIdx.z, j0 = blockIdx.x * 128, c0 = blockIdx.y * 128;
        const size_t ao = ((size_t)(b * C_ + c0)) * L_ + ch * 32;
        cpA_NT(buf, tid, v_hi + ao, v_lo + ao, L_);
        const size_t bo = ((size_t)b * L_ + ch * 32) * L_ + j0;
        cpT(buf + OFF_BHI, tid, b_hi + bo, b_lo + bo, L_, BLO_DELTA);
    }
    __device__ float scale() const { return __ldg(gamma); }
    __device__ void store2(int m, int col, float2 v) const {
        const int b = blockIdx.z, j0 = blockIdx.x * 128, c0 = blockIdx.y * 128;
        float* row = out + ((size_t)(b * C_ + c0 + m)) * L_ + j0;
        *(float2*)(row + col) = v;
    }
};

// ---------------------------------------------------------------------------
// 16-warp mma core: 128x128 CTA tile, 32x32 warp tile, 3-stage cp.async
// pipeline. Main term (hi*hi) in fp32-acc MMA; corrections (hi*lo + lo*hi)
// in a SHARED fp16-acc MMA (2x rate hypothesis), lo pre-scaled by 2^11.
// ---------------------------------------------------------------------------
template <class P>
__global__ __launch_bounds__(NTHR, 1) void mma_kernel(P prm)
{
    extern __shared__ __align__(16) char smem[];
    const unsigned sb = (unsigned)__cvta_generic_to_shared(smem);

    const int tid  = threadIdx.x;
    const int lane = tid & 31;
    const int wid  = tid >> 5;          // 0..15
    const int wm   = wid >> 2;          // 0..3 (m, 32 rows each)
    const int wn   = wid & 3;           // 0..3 (n, 32 cols each)

    float acc[2][4][4];
    u32   corr[2][4][2];
#pragma unroll
    for (int a = 0; a < 2; a++)
#pragma unroll
        for (int b = 0; b < 4; b++) {
#pragma unroll
            for (int c = 0; c < 4; c++) acc[a][b][c] = 0.f;
            corr[a][b][0] = 0u;
            corr[a][b][1] = 0u;
        }

    const unsigned mNT    = (unsigned)((lane & 7) + ((lane >> 3) & 1) * 8);
    const unsigned ksel   = (unsigned)((lane >> 4) & 1);
    const unsigned krowT  = (unsigned)(ksel * 8 + (lane & 7));
    const unsigned chalfT = (unsigned)(((lane >> 3) & 1) * 8);

    // Prologue: stage chunks 0 and 1 (one commit-group each).
    prm.issue(sb, 0, tid);
    CP_COMMIT();
    if (P::NCH > 1) prm.issue(sb + BUF_SZ, 1, tid);
    CP_COMMIT();

    int stage = 0;                       // ch % NSTAGE
    int wstage = 2;                      // (ch+2) % NSTAGE
    for (int ch = 0; ch < P::NCH; ch++) {
        cp_wait1();                      // chunk ch landed
        __syncthreads();                 // all warps done reading buf[wstage]

        // Prefetch chunk ch+2 now (buf freed by the barrier above).
        if (ch + 2 < P::NCH)
            prm.issue(sb + (unsigned)wstage * BUF_SZ, ch + 2, tid);
        CP_COMMIT();                     // empty group when nothing issued

        const unsigned base = sb + (unsigned)stage * BUF_SZ;

#pragma unroll
        for (int ks = 0; ks < 2; ks++) {
            unsigned bh[2][4], bl[2][4];
            const unsigned kbB = ((unsigned)(ks * 16) + krowT) * ST_STRIDE;
#pragma unroll
            for (int n2 = 0; n2 < 2; n2++) {
                const unsigned col = ((unsigned)(wn * 32 + n2 * 16) + chalfT) * 2u;
                ldsm4t(bh[n2], base + OFF_BHI + kbB + col);
                ldsm4t(bl[n2], base + OFF_BLO + kbB + col);
            }
#pragma unroll
            for (int mi = 0; mi < 2; mi++) {
                unsigned ah4[4], al4[4];
                if (P::A_T) {
                    const unsigned kb  = ((unsigned)(ks * 16) + krowT) * ST_STRIDE;
                    const unsigned col = ((unsigned)(wm * 32 + mi * 16) + chalfT) * 2u;
                    ldsm4t(ah4, base + kb + col);
                    ldsm4t(al4, base + OFF_ALO + kb + col);
                } else {
                    const unsigned row = (unsigned)(wm * 32 + mi * 16) + mNT;
                    const unsigned o   = row * SA_STRIDE + (unsigned)(ks * 32) + ksel * 16u;
                    ldsm4(ah4, base + o);
                    ldsm4(al4, base + OFF_ALO + o);
                }
                // Main term: hi*hi in fp32 accumulate
                mma_f32acc(acc[mi][0], ah4, bh[0][0], bh[0][2]);
                mma_f32acc(acc[mi][1], ah4, bh[0][1], bh[0][3]);
                mma_f32acc(acc[mi][2], ah4, bh[1][0], bh[1][2]);
                mma_f32acc(acc[mi][3], ah4, bh[1][1], bh[1][3]);

                // Corrections: hi*lo + lo*hi in fp16 accumulate (shared acc)
                mma_f16acc(corr[mi][0], ah4, bl[0][0], bl[0][2]);
                mma_f16acc(corr[mi][1], ah4, bl[0][1], bl[0][3]);
                mma_f16acc(corr[mi][2], ah4, bl[1][0], bl[1][2]);
                mma_f16acc(corr[mi][3], ah4, bl[1][1], bl[1][3]);

                mma_f16acc(corr[mi][0], al4, bh[0][0], bh[0][2]);
                mma_f16acc(corr[mi][1], al4, bh[0][1], bh[0][3]);
                mma_f16acc(corr[mi][2], al4, bh[1][0], bh[1][2]);
                mma_f16acc(corr[mi][3], al4, bh[1][1], bh[1][3]);
            }
        }

        stage  = (stage  == NSTAGE - 1) ? 0 : stage + 1;
        wstage = (wstage == NSTAGE - 1) ? 0 : wstage + 1;
    }

    const float s = prm.scale();
#pragma unroll
    for (int mi = 0; mi < 2; mi++) {
#pragma unroll
        for (int rr = 0; rr < 2; rr++) {
            const int r = wm * 32 + mi * 16 + (lane >> 2) + rr * 8;
#pragma unroll
            for (int ni = 0; ni < 4; ni++) {
                const int col = wn * 32 + ni * 8 + (lane & 3) * 2;
                float c0, c1;
                h2f2(corr[mi][ni][rr], c0, c1);
                float2 v;
                v.x = (acc[mi][ni][2 * rr]     + c0 * LO_INV) * s;
                v.y = (acc[mi][ni][2 * rr + 1] + c1 * LO_INV) * s;
                prm.store2(r, col, v);
            }
        }
    }
}

// ---------------------------------------------------------------------------
// Softmax over axis i of g_s[b, i, j]; writes beta as fp16 hi/lo (lo scaled).
// ---------------------------------------------------------------------------
__global__ __launch_bounds__(256) void softmax_kernel()
{
    __shared__ float redm[256];
    __shared__ float reds[256];

    const int b  = blockIdx.y;
    const int j0 = blockIdx.x * 32;
    const int tid = threadIdx.x;
    const int jj = tid & 31;
    const int ig = tid >> 5;

    const size_t cb = (size_t)b * L_ * L_ + j0 + jj;
    const float* sbp = g_s + cb;

    float m0 = -1e30f, s0 = 0.f, m1 = -1e30f, s1 = 0.f;
    for (int i = ig; i < L_; i += 16) {
        const float v0 = sbp[(size_t)i * L_];
        const float v1 = sbp[(size_t)(i + 8) * L_];
        float nm = fmaxf(m0, v0);
        s0 = s0 * __expf(m0 - nm) + __expf(v0 - nm);
        m0 = nm;
        nm = fmaxf(m1, v1);
        s1 = s1 * __expf(m1 - nm) + __expf(v1 - nm);
        m1 = nm;
    }
    {
        const float nm = fmaxf(m0, m1);
        s0 = s0 * __expf(m0 - nm) + s1 * __expf(m1 - nm);
        m0 = nm;
    }
    redm[tid] = m0;
    reds[tid] = s0;
    __syncthreads();

    float M = -1e30f, S = 0.f;
#pragma unroll
    for (int g = 0; g < 8; g++) {
        const float mm = redm[g * 32 + jj];
        const float ss = reds[g * 32 + jj];
        const float nm = fmaxf(M, mm);
        S = S * __expf(M - nm) + ss * __expf(mm - nm);
        M = nm;
    }
    const float inv = 1.f / S;

    for (int i = ig; i < L_; i += 16) {
#pragma unroll
        for (int u = 0; u < 2; u++) {
            const size_t idx = cb + (size_t)(i + u * 8) * L_;
            const float val = __expf(g_s[idx] - M) * inv;
            u16 hs;
            asm("cvt.rn.f16.f32 %0, %1;" : "=h"(hs) : "f"(val));
            float hf;
            asm("{ .reg .f16 t;\n\t mov.b16 t, %1;\n\t cvt.f32.f16 %0, t; }"
                : "=f"(hf) : "h"(hs));
            u16 ls;
            asm("cvt.rn.f16.f32 %0, %1;" : "=h"(ls) : "f"((val - hf) * LO_SCALE));
            b_hi[idx] = hs;
            b_lo[idx] = ls;
        }
    }
}

// ---------------------------------------------------------------------------
extern "C" void kernel_launch(void* const* d_in, const int* in_sizes, int n_in,
                              void* d_out, int out_size)
{
    const float* x     = (const float*)d_in[0];
    const float* Wq    = (const float*)d_in[1];
    const float* Wk    = (const float*)d_in[2];
    const float* Wv    = (const float*)d_in[3];
    const float* gamma = (const float*)d_in[4];
    float* out = (float*)d_out;

    cudaFuncSetAttribute(mma_kernel<PConv>,
                         cudaFuncAttributeMaxDynamicSharedMemorySize, SMEM_SZ);
    cudaFuncSetAttribute(mma_kernel<PScores>,
                         cudaFuncAttributeMaxDynamicSharedMemorySize, SMEM_SZ);
    cudaFuncSetAttribute(mma_kernel<POut>,
                         cudaFuncAttributeMaxDynamicSharedMemorySize, SMEM_SZ);

    prep_x  <<<B_ * C_ * L_ / 8 / 256, 256>>>(x);
    prep_wqk<<<3 * 128 * 64 / 256,     256>>>(Wq, Wk);
    prep_wv <<<3 * 512 * 64 / 256,     256>>>(Wv);

    mma_kernel<PConv>  <<<dim3(L_ / 128, 5, B_),        NTHR, SMEM_SZ>>>(PConv{});
    mma_kernel<PScores><<<dim3(L_ / 128, L_ / 128, B_), NTHR, SMEM_SZ>>>(PScores{});
    softmax_kernel     <<<dim3(L_ / 32, B_),            256>>>();
    mma_kernel<POut>   <<<dim3(L_ / 128, C_ / 128, B_), NTHR, SMEM_SZ>>>(POut{gamma, out});
}

// round 17
// speedup vs baseline: 1.1797x; 1.1568x over previous
#include <cuda_runtime.h>
#include <cuda_fp16.h>

// Problem constants
#define B_   8
#define C_   512
#define L_   2048
#define CQ_  64
#define KK_  1536

typedef unsigned short u16;
typedef unsigned int   u32;

#define LO_SCALE   2048.0f        // 2^11: keeps fp16 lo residuals in normal range
#define LO_INV     (1.0f / 2048.0f)

// ---------------------------------------------------------------------------
// Scratch (device globals — allocation-free). 16B-aligned for cp.async.
// All hi/lo arrays hold fp16; lo tiles are pre-scaled by LO_SCALE.
// ---------------------------------------------------------------------------
static __device__ __align__(16) u16 xsh_hi[3][B_ * C_ * L_];
static __device__ __align__(16) u16 xsh_lo[3][B_ * C_ * L_];
static __device__ __align__(16) u16 wqk_hi[3 * 128 * 512];   // [t][m][c], q|k rows
static __device__ __align__(16) u16 wqk_lo[3 * 128 * 512];
static __device__ __align__(16) u16 wv_hi[3 * 512 * 512];    // [t][m][c]
static __device__ __align__(16) u16 wv_lo[3 * 512 * 512];    // (unused by 2-term v-conv)
static __device__ __align__(16) u16 q_hi[B_ * CQ_ * L_], q_lo[B_ * CQ_ * L_];
static __device__ __align__(16) u16 k_hi[B_ * CQ_ * L_], k_lo[B_ * CQ_ * L_];
static __device__ __align__(16) u16 v_hi[B_ * C_ * L_],  v_lo[B_ * C_ * L_];
static __device__ float g_s[B_ * L_ * L_];                   // scores (fp32)
static __device__ __align__(16) u16 b_hi[B_ * L_ * L_];      // beta fp16 (no lo)

// SMEM stage layout (per stage):
//   A_hi @ 0      A_lo @ 10240    (NT: 128 rows x 80B; T: 32 rows x 272B)
//   B_hi @ 20480  B_lo @ 29184    (T: 32 k-rows x 272B)
#define SA_STRIDE 80u
#define ST_STRIDE 272u
#define OFF_ALO  10240u
#define OFF_BHI  20480u
#define OFF_BLO  29184u
#define BLO_DELTA 8704u          // OFF_BLO - OFF_BHI
#define BUF_SZ   37888u
#define NSTAGE   3
#define SMEM_SZ  (NSTAGE * 37888)   // 113664 B/CTA -> 1 CTA x 512 thr/SM
#define NTHR     512

// ---------------------------------------------------------------------------
// PTX helpers
// ---------------------------------------------------------------------------
static __device__ __forceinline__ void ldsm4(unsigned r[4], unsigned addr) {
    asm volatile("ldmatrix.sync.aligned.m8n8.x4.shared.b16 {%0,%1,%2,%3}, [%4];"
                 : "=r"(r[0]), "=r"(r[1]), "=r"(r[2]), "=r"(r[3]) : "r"(addr));
}
static __device__ __forceinline__ void ldsm4t(unsigned r[4], unsigned addr) {
    asm volatile("ldmatrix.sync.aligned.m8n8.x4.trans.shared.b16 {%0,%1,%2,%3}, [%4];"
                 : "=r"(r[0]), "=r"(r[1]), "=r"(r[2]), "=r"(r[3]) : "r"(addr));
}
// fp16 operands, fp32 accumulator (main term)
static __device__ __forceinline__ void mma_f32acc(float d[4], const unsigned a[4],
                                                  unsigned b0, unsigned b1) {
    asm volatile(
        "mma.sync.aligned.m16n8k16.row.col.f32.f16.f16.f32 "
        "{%0,%1,%2,%3}, {%4,%5,%6,%7}, {%8,%9}, {%0,%1,%2,%3};"
        : "+f"(d[0]), "+f"(d[1]), "+f"(d[2]), "+f"(d[3])
        : "r"(a[0]), "r"(a[1]), "r"(a[2]), "r"(a[3]), "r"(b0), "r"(b1));
}
// fp16 operands, fp16 accumulator (correction terms)
static __device__ __forceinline__ void mma_f16acc(u32 d[2], const unsigned a[4],
                                                  unsigned b0, unsigned b1) {
    asm volatile(
        "mma.sync.aligned.m16n8k16.row.col.f16.f16.f16.f16 "
        "{%0,%1}, {%2,%3,%4,%5}, {%6,%7}, {%0,%1};"
        : "+r"(d[0]), "+r"(d[1])
        : "r"(a[0]), "r"(a[1]), "r"(a[2]), "r"(a[3]), "r"(b0), "r"(b1));
}
static __device__ __forceinline__ void cpa16(unsigned s, const void* g) {
    asm volatile("cp.async.cg.shared.global [%0], [%1], 16;" :: "r"(s), "l"(g));
}
#define CP_COMMIT() asm volatile("cp.async.commit_group;" ::: "memory")
static __device__ __forceinline__ void cp_wait1() {
    asm volatile("cp.async.wait_group 1;" ::: "memory");
}

// fp32 pair -> hi (rn fp16) + lo (rn fp16 of residual, scaled by LO_SCALE)
static __device__ __forceinline__ void split_pack(float a0, float a1, u32& h, u32& l) {
    asm("cvt.rn.f16x2.f32 %0, %1, %2;" : "=r"(h) : "f"(a1), "f"(a0));
    float h0, h1;
    asm("{ .reg .f16 lo, hi;\n\t mov.b32 {lo, hi}, %2;\n\t"
        "cvt.f32.f16 %0, lo;\n\t cvt.f32.f16 %1, hi; }"
        : "=f"(h0), "=f"(h1) : "r"(h));
    asm("cvt.rn.f16x2.f32 %0, %1, %2;"
        : "=r"(l) : "f"((a1 - h1) * LO_SCALE), "f"((a0 - h0) * LO_SCALE));
}
static __device__ __forceinline__ void pack8(const float* v, uint4& H, uint4& L) {
    u32 h[4], l[4];
#pragma unroll
    for (int i = 0; i < 4; i++) split_pack(v[2 * i], v[2 * i + 1], h[i], l[i]);
    H = make_uint4(h[0], h[1], h[2], h[3]);
    L = make_uint4(l[0], l[1], l[2], l[3]);
}
static __device__ __forceinline__ void h2f2(u32 c, float& c0, float& c1) {
    asm("{ .reg .f16 lo, hi;\n\t mov.b32 {lo, hi}, %2;\n\t"
        "cvt.f32.f16 %0, lo;\n\t cvt.f32.f16 %1, hi; }"
        : "=f"(c0), "=f"(c1) : "r"(c));
}

// ---------------------------------------------------------------------------
// Prep kernels
// ---------------------------------------------------------------------------
__global__ __launch_bounds__(256) void prep_x(const float* __restrict__ x)
{
    const int idx = blockIdx.x * 256 + threadIdx.x;      // over B*C*L/8
    const int base = idx * 8;
    const int row = base >> 11;                          // b*C + c
    const int l = base & (L_ - 1);
    const float* xr = x + (size_t)row * L_;

    float v[10];
    *(float4*)(v + 1) = *(const float4*)(xr + l);
    *(float4*)(v + 5) = *(const float4*)(xr + l + 4);
    v[0] = (l > 0) ? xr[l - 1] : 0.f;
    v[9] = (l + 8 < L_) ? xr[l + 8] : 0.f;

    const size_t o = (size_t)row * L_ + l;
#pragma unroll
    for (int t = 0; t < 3; t++) {        // xsh[t][j] = x[j + t - 1]
        uint4 H, L;
        pack8(v + t, H, L);
        *(uint4*)(&xsh_hi[t][o]) = H;
        *(uint4*)(&xsh_lo[t][o]) = L;
    }
}

__global__ __launch_bounds__(256) void prep_wqk(const float* __restrict__ Wq,
                                                const float* __restrict__ Wk)
{
    const int idx = blockIdx.x * 256 + threadIdx.x;      // 3*128*64
    const int c8 = idx & 63, m = (idx >> 6) & 127, t = idx >> 13;
    const float* src = ((m < CQ_) ? (Wq + m * KK_) : (Wk + (m - CQ_) * KK_)) + c8 * 24 + t;
    float v[8];
#pragma unroll
    for (int i = 0; i < 8; i++) v[i] = src[i * 3];
    uint4 H, L;
    pack8(v, H, L);
    const int o = (t * 128 + m) * 512 + c8 * 8;
    *(uint4*)(&wqk_hi[o]) = H;
    *(uint4*)(&wqk_lo[o]) = L;
}

__global__ __launch_bounds__(256) void prep_wv(const float* __restrict__ Wv)
{
    const int idx = blockIdx.x * 256 + threadIdx.x;      // 3*512*64
    const int c8 = idx & 63, m = (idx >> 6) & 511, t = idx >> 15;
    const float* src = Wv + m * KK_ + c8 * 24 + t;
    float v[8];
#pragma unroll
    for (int i = 0; i < 8; i++) v[i] = src[i * 3];
    uint4 H, L;
    pack8(v, H, L);
    const int o = (t * 512 + m) * 512 + c8 * 8;
    *(uint4*)(&wv_hi[o]) = H;
    *(uint4*)(&wv_lo[o]) = L;
}

// ---------------------------------------------------------------------------
// cp.async tile issue helpers (512 threads: one 16B cp per tile per thread)
// ---------------------------------------------------------------------------
static __device__ __forceinline__ void cpA_NT(unsigned buf, int tid,
                                              const u16* hi, const u16* lo,
                                              size_t rstride, bool load_lo) {
    const int m = tid >> 2, s = tid & 3;                 // 128 rows x 4 segs
    const unsigned sm = buf + (unsigned)m * SA_STRIDE + (unsigned)s * 16u;
    const size_t go = (size_t)m * rstride + s * 8;
    cpa16(sm, hi + go);
    if (load_lo) cpa16(sm + OFF_ALO, lo + go);
}
// ldelta = smem distance from hi tile to lo tile (A: OFF_ALO, B: BLO_DELTA).
static __device__ __forceinline__ void cpT(unsigned buf, int tid,
                                           const u16* hi, const u16* lo,
                                           size_t rstride, unsigned ldelta,
                                           bool load_lo) {
    const int kc = tid >> 4, s = tid & 15;               // 32 k-rows x 16 segs
    const unsigned sm = buf + (unsigned)kc * ST_STRIDE + (unsigned)s * 16u;
    const size_t go = (size_t)kc * rstride + s * 8;
    cpa16(sm, hi + go);
    if (load_lo) cpa16(sm + ldelta, lo + go);
}

// ---------------------------------------------------------------------------
// Per-problem structs. use_al: add Al*Bh term; use_bl: add Ah*Bl term.
// ---------------------------------------------------------------------------
struct PConv {                   // merged conv: y=0..3 -> v rows, y=4 -> q|k rows
    static constexpr int NCH = 48;
    static constexpr bool A_T = false;
    __device__ bool use_al() const { return blockIdx.y == 4; }  // W_lo only for q|k
    __device__ bool use_bl() const { return true; }             // x_lo always
    __device__ void issue(unsigned buf, int ch, int tid) const {
        const int b = blockIdx.z, l0 = blockIdx.x * 128, y = blockIdx.y;
        const int t = ch >> 4, c0 = (ch & 15) * 32;
        const u16* Ah;
        const u16* Al;
        if (y == 4) {
            Ah = wqk_hi + (t * 128) * 512 + c0;
            Al = wqk_lo + (t * 128) * 512 + c0;
        } else {
            Ah = wv_hi + (t * 512 + y * 128) * 512 + c0;
            Al = Ah;                                   // unused (use_al false)
        }
        cpA_NT(buf, tid, Ah, Al, 512, y == 4);
        const size_t bo = ((size_t)(b * C_ + c0)) * L_ + l0;
        cpT(buf + OFF_BHI, tid, xsh_hi[t] + bo, xsh_lo[t] + bo, L_, BLO_DELTA, true);
    }
    __device__ float scale() const { return 1.f; }
    __device__ void store2(int m, int col, float2 v) const {
        const int b = blockIdx.z, l0 = blockIdx.x * 128, y = blockIdx.y;
        u32 h, l;
        split_pack(v.x, v.y, h, l);
        if (y == 4) {
            const size_t off = ((size_t)(b * CQ_ + (m & 63))) * L_ + l0 + col;
            if (m < CQ_) { *(u32*)(q_hi + off) = h; *(u32*)(q_lo + off) = l; }
            else         { *(u32*)(k_hi + off) = h; *(u32*)(k_lo + off) = l; }
        } else {
            const size_t off = ((size_t)(b * C_ + y * 128 + m)) * L_ + l0 + col;
            *(u32*)(v_hi + off) = h;
            *(u32*)(v_lo + off) = l;
        }
    }
};

struct PScores {                 // D[i,j] = sum_c q[c,i]*k[c,j], K=64 — full 3-term
    static constexpr int NCH = 2;
    static constexpr bool A_T = true;
    __device__ bool use_al() const { return true; }
    __device__ bool use_bl() const { return true; }
    __device__ void issue(unsigned buf, int ch, int tid) const {
        const int b = blockIdx.z, j0 = blockIdx.x * 128, i0 = blockIdx.y * 128;
        const size_t ao = ((size_t)(b * CQ_ + ch * 32)) * L_ + i0;
        cpT(buf,           tid, q_hi + ao, q_lo + ao, L_, OFF_ALO, true);
        const size_t bo = ((size_t)(b * CQ_ + ch * 32)) * L_ + j0;
        cpT(buf + OFF_BHI, tid, k_hi + bo, k_lo + bo, L_, BLO_DELTA, true);
    }
    __device__ float scale() const { return 1.f; }
    __device__ void store2(int m, int col, float2 v) const {
        const int b = blockIdx.z, j0 = blockIdx.x * 128, i0 = blockIdx.y * 128;
        float* row = g_s + (size_t)b * L_ * L_ + (size_t)(i0 + m) * L_ + j0;
        *(float2*)(row + col) = v;
    }
};

struct POut {                    // out[c,j] = gamma * sum_l v[c,l]*beta[l,j]
    const float* gamma;          // 2-term: (vh+vl)*beta_hi — beta lo dropped
    float* out;
    static constexpr int NCH = 64;
    static constexpr bool A_T = false;
    __device__ bool use_al() const { return true; }
    __device__ bool use_bl() const { return false; }
    __device__ void issue(unsigned buf, int ch, int tid) const {
        const int b = blockIdx.z, j0 = blockIdx.x * 128, c0 = blockIdx.y * 128;
        const size_t ao = ((size_t)(b * C_ + c0)) * L_ + ch * 32;
        cpA_NT(buf, tid, v_hi + ao, v_lo + ao, L_, true);
        const size_t bo = ((size_t)b * L_ + ch * 32) * L_ + j0;
        cpT(buf + OFF_BHI, tid, b_hi + bo, b_hi + bo, L_, BLO_DELTA, false);
    }
    __device__ float scale() const { return __ldg(gamma); }
    __device__ void store2(int m, int col, float2 v) const {
        const int b = blockIdx.z, j0 = blockIdx.x * 128, c0 = blockIdx.y * 128;
        float* row = out + ((size_t)(b * C_ + c0 + m)) * L_ + j0;
        *(float2*)(row + col) = v;
    }
};

// ---------------------------------------------------------------------------
// 16-warp mma core: 128x128 CTA tile, 32x32 warp tile, 3-stage cp.async
// pipeline. hi*hi in fp32-acc; optional corrections (Ah*Bl, Al*Bh) in fp16-acc
// with lo pre-scaled by 2^11. Term set per problem via use_al()/use_bl().
// ---------------------------------------------------------------------------
template <class P>
__global__ __launch_bounds__(NTHR, 1) void mma_kernel(P prm)
{
    extern __shared__ __align__(16) char smem[];
    const unsigned sb = (unsigned)__cvta_generic_to_shared(smem);

    const int tid  = threadIdx.x;
    const int lane = tid & 31;
    const int wid  = tid >> 5;          // 0..15
    const int wm   = wid >> 2;          // 0..3 (m, 32 rows each)
    const int wn   = wid & 3;           // 0..3 (n, 32 cols each)

    const bool uAL = prm.use_al();
    const bool uBL = prm.use_bl();

    float acc[2][4][4];
    u32   corr[2][4][2];
#pragma unroll
    for (int a = 0; a < 2; a++)
#pragma unroll
        for (int b = 0; b < 4; b++) {
#pragma unroll
            for (int c = 0; c < 4; c++) acc[a][b][c] = 0.f;
            corr[a][b][0] = 0u;
            corr[a][b][1] = 0u;
        }

    const unsigned mNT    = (unsigned)((lane & 7) + ((lane >> 3) & 1) * 8);
    const unsigned ksel   = (unsigned)((lane >> 4) & 1);
    const unsigned krowT  = (unsigned)(ksel * 8 + (lane & 7));
    const unsigned chalfT = (unsigned)(((lane >> 3) & 1) * 8);

    // Prologue: stage chunks 0 and 1 (one commit-group each).
    prm.issue(sb, 0, tid);
    CP_COMMIT();
    if (P::NCH > 1) prm.issue(sb + BUF_SZ, 1, tid);
    CP_COMMIT();

    int stage = 0;                       // ch % NSTAGE
    int wstage = 2;                      // (ch+2) % NSTAGE
    for (int ch = 0; ch < P::NCH; ch++) {
        cp_wait1();                      // chunk ch landed
        __syncthreads();                 // all warps done reading buf[wstage]

        // Prefetch chunk ch+2 now (buf freed by the barrier above).
        if (ch + 2 < P::NCH)
            prm.issue(sb + (unsigned)wstage * BUF_SZ, ch + 2, tid);
        CP_COMMIT();                     // empty group when nothing issued

        const unsigned base = sb + (unsigned)stage * BUF_SZ;

#pragma unroll
        for (int ks = 0; ks < 2; ks++) {
            unsigned bh[2][4], bl[2][4];
            const unsigned kbB = ((unsigned)(ks * 16) + krowT) * ST_STRIDE;
#pragma unroll
            for (int n2 = 0; n2 < 2; n2++) {
                const unsigned col = ((unsigned)(wn * 32 + n2 * 16) + chalfT) * 2u;
                ldsm4t(bh[n2], base + OFF_BHI + kbB + col);
                if (uBL) ldsm4t(bl[n2], base + OFF_BLO + kbB + col);
            }
#pragma unroll
            for (int mi = 0; mi < 2; mi++) {
                unsigned ah4[4], al4[4];
                if (P::A_T) {
                    const unsigned kb  = ((unsigned)(ks * 16) + krowT) * ST_STRIDE;
                    const unsigned col = ((unsigned)(wm * 32 + mi * 16) + chalfT) * 2u;
                    ldsm4t(ah4, base + kb + col);
                    if (uAL) ldsm4t(al4, base + OFF_ALO + kb + col);
                } else {
                    const unsigned row = (unsigned)(wm * 32 + mi * 16) + mNT;
                    const unsigned o   = row * SA_STRIDE + (unsigned)(ks * 32) + ksel * 16u;
                    ldsm4(ah4, base + o);
                    if (uAL) ldsm4(al4, base + OFF_ALO + o);
                }
                // Main term: hi*hi in fp32 accumulate
                mma_f32acc(acc[mi][0], ah4, bh[0][0], bh[0][2]);
                mma_f32acc(acc[mi][1], ah4, bh[0][1], bh[0][3]);
                mma_f32acc(acc[mi][2], ah4, bh[1][0], bh[1][2]);
                mma_f32acc(acc[mi][3], ah4, bh[1][1], bh[1][3]);

                if (uBL) {               // Ah * Bl
                    mma_f16acc(corr[mi][0], ah4, bl[0][0], bl[0][2]);
                    mma_f16acc(corr[mi][1], ah4, bl[0][1], bl[0][3]);
                    mma_f16acc(corr[mi][2], ah4, bl[1][0], bl[1][2]);
                    mma_f16acc(corr[mi][3], ah4, bl[1][1], bl[1][3]);
                }
                if (uAL) {               // Al * Bh
                    mma_f16acc(corr[mi][0], al4, bh[0][0], bh[0][2]);
                    mma_f16acc(corr[mi][1], al4, bh[0][1], bh[0][3]);
                    mma_f16acc(corr[mi][2], al4, bh[1][0], bh[1][2]);
                    mma_f16acc(corr[mi][3], al4, bh[1][1], bh[1][3]);
                }
            }
        }

        stage  = (stage  == NSTAGE - 1) ? 0 : stage + 1;
        wstage = (wstage == NSTAGE - 1) ? 0 : wstage + 1;
    }

    const float s = prm.scale();
#pragma unroll
    for (int mi = 0; mi < 2; mi++) {
#pragma unroll
        for (int rr = 0; rr < 2; rr++) {
            const int r = wm * 32 + mi * 16 + (lane >> 2) + rr * 8;
#pragma unroll
            for (int ni = 0; ni < 4; ni++) {
                const int col = wn * 32 + ni * 8 + (lane & 3) * 2;
                float c0, c1;
                h2f2(corr[mi][ni][rr], c0, c1);
                float2 v;
                v.x = (acc[mi][ni][2 * rr]     + c0 * LO_INV) * s;
                v.y = (acc[mi][ni][2 * rr + 1] + c1 * LO_INV) * s;
                prm.store2(r, col, v);
            }
        }
    }
}

// ---------------------------------------------------------------------------
// Softmax over axis i of g_s[b, i, j]; writes beta as fp16 (hi only).
// ---------------------------------------------------------------------------
__global__ __launch_bounds__(256) void softmax_kernel()
{
    __shared__ float redm[256];
    __shared__ float reds[256];

    const int b  = blockIdx.y;
    const int j0 = blockIdx.x * 32;
    const int tid = threadIdx.x;
    const int jj = tid & 31;
    const int ig = tid >> 5;

    const size_t cb = (size_t)b * L_ * L_ + j0 + jj;
    const float* sbp = g_s + cb;

    float m0 = -1e30f, s0 = 0.f, m1 = -1e30f, s1 = 0.f;
    for (int i = ig; i < L_; i += 16) {
        const float v0 = sbp[(size_t)i * L_];
        const float v1 = sbp[(size_t)(i + 8) * L_];
        float nm = fmaxf(m0, v0);
        s0 = s0 * __expf(m0 - nm) + __expf(v0 - nm);
        m0 = nm;
        nm = fmaxf(m1, v1);
        s1 = s1 * __expf(m1 - nm) + __expf(v1 - nm);
        m1 = nm;
    }
    {
        const float nm = fmaxf(m0, m1);
        s0 = s0 * __expf(m0 - nm) + s1 * __expf(m1 - nm);
        m0 = nm;
    }
    redm[tid] = m0;
    reds[tid] = s0;
    __syncthreads();

    float M = -1e30f, S = 0.f;
#pragma unroll
    for (int g = 0; g < 8; g++) {
        const float mm = redm[g * 32 + jj];
        const float ss = reds[g * 32 + jj];
        const float nm = fmaxf(M, mm);
        S = S * __expf(M - nm) + ss * __expf(mm - nm);
        M = nm;
    }
    const float inv = 1.f / S;

    for (int i = ig; i < L_; i += 16) {
#pragma unroll
        for (int u = 0; u < 2; u++) {
            const size_t idx = cb + (size_t)(i + u * 8) * L_;
            const float val = __expf(g_s[idx] - M) * inv;
            u16 hs;
            asm("cvt.rn.f16.f32 %0, %1;" : "=h"(hs) : "f"(val));
            b_hi[idx] = hs;
        }
    }
}

// ---------------------------------------------------------------------------
extern "C" void kernel_launch(void* const* d_in, const int* in_sizes, int n_in,
                              void* d_out, int out_size)
{
    const float* x     = (const float*)d_in[0];
    const float* Wq    = (const float*)d_in[1];
    const float* Wk    = (const float*)d_in[2];
    const float* Wv    = (const float*)d_in[3];
    const float* gamma = (const float*)d_in[4];
    float* out = (float*)d_out;

    cudaFuncSetAttribute(mma_kernel<PConv>,
                         cudaFuncAttributeMaxDynamicSharedMemorySize, SMEM_SZ);
    cudaFuncSetAttribute(mma_kernel<PScores>,
                         cudaFuncAttributeMaxDynamicSharedMemorySize, SMEM_SZ);
    cudaFuncSetAttribute(mma_kernel<POut>,
                         cudaFuncAttributeMaxDynamicSharedMemorySize, SMEM_SZ);

    prep_x  <<<B_ * C_ * L_ / 8 / 256, 256>>>(x);
    prep_wqk<<<3 * 128 * 64 / 256,     256>>>(Wq, Wk);
    prep_wv <<<3 * 512 * 64 / 256,     256>>>(Wv);

    mma_kernel<PConv>  <<<dim3(L_ / 128, 5, B_),        NTHR, SMEM_SZ>>>(PConv{});
    mma_kernel<PScores><<<dim3(L_ / 128, L_ / 128, B_), NTHR, SMEM_SZ>>>(PScores{});
    softmax_kernel     <<<dim3(L_ / 32, B_),            256>>>();
    mma_kernel<POut>   <<<dim3(L_ / 128, C_ / 128, B_), NTHR, SMEM_SZ>>>(POut{gamma, out});
}